// round 4
// baseline (speedup 1.0000x reference)
#include <cuda_runtime.h>
#include <cuda_bf16.h>
#include <cstdint>

using bf16 = __nv_bfloat16;

// ---------------- problem constants ----------------
static constexpr int E_  = 8;
static constexpr int H_  = 1024;
static constexpr int F_  = 4096;
static constexpr int T_  = 16384;
static constexpr int TPE_ = T_ / E_;   // 2048 tokens per expert

// ---------------- GEMM tile config (shared by both ISA paths) ----------------
static constexpr int MT = 128;    // M tile
static constexpr int NT = 128;    // N tile
static constexpr int KC = 64;     // K chunk (bf16) = 128B SW128 row
static constexpr int A_BYTES = MT * 128;          // 16384 per (hi|lo)
static constexpr int B_BYTES = NT * 128;          // 16384 per (hi|lo)
static constexpr int OFF_AH = 0;
static constexpr int OFF_AL = A_BYTES;
static constexpr int OFF_BH = 2 * A_BYTES;
static constexpr int OFF_BL = 2 * A_BYTES + B_BYTES;
static constexpr int STAGE_BYTES = 2 * A_BYTES + 2 * B_BYTES;     // 65536
static constexpr int SMEM_STAGE0 = 1024;
static constexpr int SMEM_TOTAL  = SMEM_STAGE0 + 2 * STAGE_BYTES; // 132096

// ---------------- scratch (static device globals; no allocation) ----------------
__device__ bf16 g_xh[(size_t)T_ * H_];
__device__ bf16 g_xl[(size_t)T_ * H_];
__device__ bf16 g_w1h[(size_t)E_ * F_ * H_];   // transposed: [E][F][H]
__device__ bf16 g_w1l[(size_t)E_ * F_ * H_];
__device__ bf16 g_w2h[(size_t)E_ * H_ * F_];   // transposed: [E][H][F]
__device__ bf16 g_w2l[(size_t)E_ * H_ * F_];
__device__ bf16 g_ih[(size_t)T_ * F_];         // gelu(intermediate) hi
__device__ bf16 g_il[(size_t)T_ * F_];         // gelu(intermediate) lo

#define DI __device__ __forceinline__

DI uint32_t smem_u32(const void* p) {
    uint32_t a;
    asm("{ .reg .u64 t; cvta.to.shared.u64 t, %1; cvt.u32.u64 %0, t; }"
        : "=r"(a) : "l"(p));
    return a;
}

DI float gelu_tanh(float x) {  // jax.nn.gelu default (approximate=True)
    float x3 = x * x * x;
    float t = tanhf(0.7978845608028654f * (x + 0.044715f * x3));
    return 0.5f * x * (1.0f + t);
}

// Load one K-chunk stage: A(hi,lo) 128x128B + B(hi,lo) 128x128B, SW128-swizzled.
DI void load_stage(char* stg,
                   const bf16* __restrict__ Ah, const bf16* __restrict__ Al,
                   const bf16* __restrict__ Bh, const bf16* __restrict__ Bl,
                   size_t arow0, size_t brow0, int K, size_t kb, int tid) {
#pragma unroll
    for (int v = tid; v < MT * 8; v += 256) {
        int r = v >> 3, cc = v & 7;
        size_t gb = ((arow0 + r) * (size_t)K + kb) * 2 + (size_t)cc * 16;
        uint32_t so = (uint32_t)(r * 128 + cc * 16);
        so ^= (so >> 3) & 0x70;
        *(uint4*)(stg + OFF_AH + so) = *(const uint4*)((const char*)Ah + gb);
        *(uint4*)(stg + OFF_AL + so) = *(const uint4*)((const char*)Al + gb);
    }
#pragma unroll
    for (int v = tid; v < NT * 8; v += 256) {
        int r = v >> 3, cc = v & 7;
        size_t gb = ((brow0 + r) * (size_t)K + kb) * 2 + (size_t)cc * 16;
        uint32_t so = (uint32_t)(r * 128 + cc * 16);
        so ^= (so >> 3) & 0x70;
        *(uint4*)(stg + OFF_BH + so) = *(const uint4*)((const char*)Bh + gb);
        *(uint4*)(stg + OFF_BL + so) = *(const uint4*)((const char*)Bl + gb);
    }
}

#if defined(__CUDA_ARCH__) && defined(__CUDA_ARCH_FEAT_SM103_ALL)
// =================== accelerated-ISA helpers (tcgen05) ===================
DI uint32_t elect_one() {
    uint32_t pred;
    asm volatile(
        "{\n\t.reg .pred p;\n\t"
        "elect.sync _|p, 0xFFFFFFFF;\n\t"
        "selp.b32 %0, 1, 0, p;\n\t}"
        : "=r"(pred));
    return pred;
}
#define MBAR_INIT(addr, cnt) \
    asm volatile("mbarrier.init.shared.b64 [%0], %1;" :: "r"(addr), "r"((uint32_t)(cnt)) : "memory")
#define MBAR_WAIT(addr, parity) do {                                               \
    uint32_t _m = (addr); uint32_t _p = (parity); uint32_t _done;                  \
    asm volatile(                                                                  \
        "{\n\t.reg .pred p;\n\t"                                                   \
        "mbarrier.try_wait.parity.acquire.cta.shared::cta.b64 p, [%1], %2;\n\t"    \
        "selp.b32 %0, 1, 0, p;\n\t}"                                               \
        : "=r"(_done) : "r"(_m), "r"(_p) : "memory");                              \
    if (!_done) {                                                                  \
        asm volatile(                                                              \
            "{\n\t.reg .pred P1;\n\t"                                              \
            "WL_%=:\n\t"                                                           \
            "mbarrier.try_wait.parity.acquire.cta.shared::cta.b64 P1, [%0], %1, 0x989680;\n\t" \
            "@P1 bra.uni WD_%=;\n\t"                                               \
            "bra.uni WL_%=;\n\t"                                                   \
            "WD_%=:\n\t}"                                                          \
            :: "r"(_m), "r"(_p) : "memory");                                       \
    }                                                                              \
} while (0)
#define TCG_ALLOC(smem_addr, ncols) \
    asm volatile("tcgen05.alloc.cta_group::1.sync.aligned.shared::cta.b32 [%0], %1;" \
                 :: "r"(smem_addr), "r"((uint32_t)(ncols)) : "memory")
#define TCG_DEALLOC(tmem_addr, ncols) \
    asm volatile("tcgen05.dealloc.cta_group::1.sync.aligned.b32 %0, %1;" \
                 :: "r"(tmem_addr), "r"((uint32_t)(ncols)))
#define TCG_COMMIT(mbar_addr) \
    asm volatile("tcgen05.commit.cta_group::1.mbarrier::arrive::one.shared::cluster.b64 [%0];" \
                 :: "r"(mbar_addr) : "memory")
#define TCG_WAIT_LD() asm volatile("tcgen05.wait::ld.sync.aligned;" ::: "memory")
#define TCG_FENCE_AFTER() asm volatile("tcgen05.fence::after_thread_sync;" ::: "memory")
#define FENCE_ASYNC_SHARED() asm volatile("fence.proxy.async.shared::cta;" ::: "memory")
#define TCG_LD_X32(r, tmem_addr)                                                   \
    asm volatile(                                                                  \
        "tcgen05.ld.sync.aligned.32x32b.x32.b32 "                                  \
        "{%0, %1, %2, %3, %4, %5, %6, %7, "                                        \
        " %8, %9, %10, %11, %12, %13, %14, %15, "                                  \
        " %16, %17, %18, %19, %20, %21, %22, %23, "                                \
        " %24, %25, %26, %27, %28, %29, %30, %31}, [%32];"                         \
        : "=r"((r)[0]),  "=r"((r)[1]),  "=r"((r)[2]),  "=r"((r)[3]),               \
          "=r"((r)[4]),  "=r"((r)[5]),  "=r"((r)[6]),  "=r"((r)[7]),               \
          "=r"((r)[8]),  "=r"((r)[9]),  "=r"((r)[10]), "=r"((r)[11]),              \
          "=r"((r)[12]), "=r"((r)[13]), "=r"((r)[14]), "=r"((r)[15]),              \
          "=r"((r)[16]), "=r"((r)[17]), "=r"((r)[18]), "=r"((r)[19]),              \
          "=r"((r)[20]), "=r"((r)[21]), "=r"((r)[22]), "=r"((r)[23]),              \
          "=r"((r)[24]), "=r"((r)[25]), "=r"((r)[26]), "=r"((r)[27]),              \
          "=r"((r)[28]), "=r"((r)[29]), "=r"((r)[30]), "=r"((r)[31])               \
        : "r"(tmem_addr))

static constexpr uint32_t IDESC =
    (1u << 4) | (1u << 7) | (1u << 10) | ((NT / 8) << 17) | ((MT / 16) << 24);
static constexpr uint64_t DESC_BASE =
    (uint64_t(2) << 61) | (uint64_t(1) << 46) | (uint64_t(64) << 32) | (uint64_t(1) << 16);
DI uint64_t make_desc(uint32_t addr) { return DESC_BASE | ((addr >> 4) & 0x3FFFu); }

DI void mma_ss_f16(uint32_t d, uint64_t a_desc, uint64_t b_desc, uint32_t idesc, bool acc) {
    uint32_t en = acc ? 1u : 0u;
    asm volatile(
        "{\n\t.reg .pred p;\n\t"
        "setp.ne.u32 p, %5, 0;\n\t"
        "tcgen05.mma.cta_group::1.kind::f16 [%0], %1, %2, %3, {%4, %4, %4, %4}, p;\n\t}"
        :: "r"(d), "l"(a_desc), "l"(b_desc), "r"(idesc), "r"(0u), "r"(en)
        : "memory");
}
#else
// =================== base-ISA helpers (ldmatrix + mma.sync) ===================
#define LDSM_X4(r, addr)                                                           \
    asm volatile("ldmatrix.sync.aligned.m8n8.x4.shared.b16 {%0, %1, %2, %3}, [%4];" \
        : "=r"((r)[0]), "=r"((r)[1]), "=r"((r)[2]), "=r"((r)[3]) : "r"(addr))

DI void mma16816(float* c, const uint32_t* a, const uint32_t* b) {
    asm volatile(
        "mma.sync.aligned.m16n8k16.row.col.f32.bf16.bf16.f32 "
        "{%0, %1, %2, %3}, {%4, %5, %6, %7}, {%8, %9}, {%0, %1, %2, %3};"
        : "+f"(c[0]), "+f"(c[1]), "+f"(c[2]), "+f"(c[3])
        : "r"(a[0]), "r"(a[1]), "r"(a[2]), "r"(a[3]), "r"(b[0]), "r"(b[1]));
}
#endif

// ---------------- prep kernels ----------------
__global__ void k_split(const float4* __restrict__ in,
                        __nv_bfloat162* __restrict__ oh,
                        __nv_bfloat162* __restrict__ ol, int n4) {
    int i = blockIdx.x * blockDim.x + threadIdx.x;
    if (i >= n4) return;
    float4 v = in[i];
    bf16 h0 = __float2bfloat16(v.x), h1 = __float2bfloat16(v.y);
    bf16 h2 = __float2bfloat16(v.z), h3 = __float2bfloat16(v.w);
    bf16 l0 = __float2bfloat16(v.x - __bfloat162float(h0));
    bf16 l1 = __float2bfloat16(v.y - __bfloat162float(h1));
    bf16 l2 = __float2bfloat16(v.z - __bfloat162float(h2));
    bf16 l3 = __float2bfloat16(v.w - __bfloat162float(h3));
    __nv_bfloat162 a, b, c, d;
    a.x = h0; a.y = h1; b.x = h2; b.y = h3;
    c.x = l0; c.y = l1; d.x = l2; d.y = l3;
    oh[2 * i] = a; oh[2 * i + 1] = b;
    ol[2 * i] = c; ol[2 * i + 1] = d;
}

__global__ void k_transpose_split(const float* __restrict__ in,
                                  bf16* __restrict__ oh, bf16* __restrict__ ol,
                                  int R, int C) {
    __shared__ float tile[32][33];
    size_t base = (size_t)blockIdx.z * R * C;
    int r0 = blockIdx.y * 32, c0 = blockIdx.x * 32;
    int tx = threadIdx.x, ty = threadIdx.y;
#pragma unroll
    for (int i = ty; i < 32; i += 8)
        tile[i][tx] = in[base + (size_t)(r0 + i) * C + c0 + tx];
    __syncthreads();
#pragma unroll
    for (int i = ty; i < 32; i += 8) {
        float v = tile[tx][i];
        size_t o = base + (size_t)(c0 + i) * R + r0 + tx;
        bf16 h = __float2bfloat16(v);
        oh[o] = h;
        ol[o] = __float2bfloat16(v - __bfloat162float(h));
    }
}

// ---------------- grouped split-bf16 GEMM (dual ISA path) ----------------
// D[128x128] tile = sum_k (Ah*Bh + Ah*Bl + Al*Bh), fp32 accum.
// A: [E*rowsA_pe, K] K-major bf16 (hi/lo).  B: [E*rowsB_pe, K] K-major bf16 (hi/lo).
template <bool GELU_SPLIT>
__global__ void __launch_bounds__(256, 1)
k_gemm(const bf16* __restrict__ Ah, const bf16* __restrict__ Al,
       const bf16* __restrict__ Bh, const bf16* __restrict__ Bl,
       int K, int rowsA_pe, int rowsB_pe,
       bf16* __restrict__ Oh, bf16* __restrict__ Ol,
       float* __restrict__ Of, int ldo) {
    extern __shared__ char smem[];
    uint32_t sb = smem_u32(smem);
    int tid = threadIdx.x, wid = tid >> 5, lid = tid & 31;

    size_t arow0 = (size_t)blockIdx.z * rowsA_pe + (size_t)blockIdx.y * MT;
    size_t brow0 = (size_t)blockIdx.z * rowsB_pe + (size_t)blockIdx.x * NT;
    size_t ncol0 = (size_t)blockIdx.x * NT;
    const int NC = K / KC;

#if defined(__CUDA_ARCH__) && defined(__CUDA_ARCH_FEAT_SM103_ALL)
    // ---------------- tcgen05 path ----------------
    if (wid == 0) TCG_ALLOC(sb, 128);
    if (tid == 0) { MBAR_INIT(sb + 16, 1); MBAR_INIT(sb + 24, 1); }
    __syncthreads();
    uint32_t tmem;
    asm volatile("ld.shared.b32 %0, [%1];" : "=r"(tmem) : "r"(sb));

    int ph0 = 0, ph1 = 0;
    for (int c = 0; c < NC; ++c) {
        int s = c & 1;
        char* stg = smem + SMEM_STAGE0 + s * STAGE_BYTES;
        uint32_t stg_u = sb + SMEM_STAGE0 + s * STAGE_BYTES;
        if (c >= 2) {
            if (s == 0) { MBAR_WAIT(sb + 16, ph0); ph0 ^= 1; }
            else        { MBAR_WAIT(sb + 24, ph1); ph1 ^= 1; }
        }
        load_stage(stg, Ah, Al, Bh, Bl, arow0, brow0, K, (size_t)c * KC, tid);
        FENCE_ASYNC_SHARED();
        __syncthreads();
        if (wid == 0 && elect_one()) {
            uint64_t dAh = make_desc(stg_u + OFF_AH), dAl = make_desc(stg_u + OFF_AL);
            uint64_t dBh = make_desc(stg_u + OFF_BH), dBl = make_desc(stg_u + OFF_BL);
#pragma unroll
            for (int ks = 0; ks < KC / 16; ++ks)
                mma_ss_f16(tmem, dAh + ks * 2, dBh + ks * 2, IDESC, !(c == 0 && ks == 0));
#pragma unroll
            for (int ks = 0; ks < KC / 16; ++ks)
                mma_ss_f16(tmem, dAh + ks * 2, dBl + ks * 2, IDESC, true);
#pragma unroll
            for (int ks = 0; ks < KC / 16; ++ks)
                mma_ss_f16(tmem, dAl + ks * 2, dBh + ks * 2, IDESC, true);
            TCG_COMMIT(s == 0 ? sb + 16 : sb + 24);
        }
    }
    MBAR_WAIT(sb + 16, ph0);
    MBAR_WAIT(sb + 24, ph1);
    TCG_FENCE_AFTER();

    if (tid < 128) {
        size_t grow = arow0 + (size_t)(wid * 32 + lid);
#pragma unroll 1
        for (int blk = 0; blk < NT / 32; ++blk) {
            uint32_t regs[32];
            TCG_LD_X32(regs, tmem + blk * 32);
            TCG_WAIT_LD();
            if (GELU_SPLIT) {
#pragma unroll
                for (int j = 0; j < 32; j += 2) {
                    float g0 = gelu_tanh(__uint_as_float(regs[j]));
                    float g1 = gelu_tanh(__uint_as_float(regs[j + 1]));
                    bf16 h0 = __float2bfloat16(g0), h1 = __float2bfloat16(g1);
                    bf16 l0 = __float2bfloat16(g0 - __bfloat162float(h0));
                    bf16 l1 = __float2bfloat16(g1 - __bfloat162float(h1));
                    size_t o = grow * (size_t)ldo + ncol0 + blk * 32 + j;
                    __nv_bfloat162 hp, lp;
                    hp.x = h0; hp.y = h1; lp.x = l0; lp.y = l1;
                    *(__nv_bfloat162*)(Oh + o) = hp;
                    *(__nv_bfloat162*)(Ol + o) = lp;
                }
            } else {
#pragma unroll
                for (int j = 0; j < 32; j += 4) {
                    float4 vv;
                    vv.x = __uint_as_float(regs[j]);
                    vv.y = __uint_as_float(regs[j + 1]);
                    vv.z = __uint_as_float(regs[j + 2]);
                    vv.w = __uint_as_float(regs[j + 3]);
                    *(float4*)(Of + grow * (size_t)ldo + ncol0 + blk * 32 + j) = vv;
                }
            }
        }
    }
    __syncthreads();
    if (wid == 0) TCG_DEALLOC(tmem, 128);
#else
    // ---------------- base-ISA path: ldmatrix + mma.sync (HMMA) ----------------
    // 8 warps: warp tile 64x32; warp grid 2(M) x 4(N).
    int m_off = (wid & 1) * 64;
    int n_off = (wid >> 1) * 32;
    uint32_t xorv = (uint32_t)(lid & 7) << 4;            // SW128 per-row XOR
    uint32_t a_row = (lid & 7) + ((lid >> 3) & 1) * 8;   // row within m16 tile
    uint32_t a_kx  = (uint32_t)(lid >> 4) * 16;          // k-byte offset (0/16)
    uint32_t b_row = (lid & 7) + ((lid >> 4) & 1) * 8;   // row within n16 pair
    uint32_t b_kx  = ((uint32_t)(lid >> 3) & 1) * 16;

    float acc[4][4][4];
#pragma unroll
    for (int mt = 0; mt < 4; ++mt)
#pragma unroll
        for (int nt = 0; nt < 4; ++nt)
#pragma unroll
            for (int r = 0; r < 4; ++r) acc[mt][nt][r] = 0.0f;

    load_stage(smem + SMEM_STAGE0, Ah, Al, Bh, Bl, arow0, brow0, K, 0, tid);

    for (int c = 0; c < NC; ++c) {
        __syncthreads();   // stage c ready; stage (c+1)&1 free for writing
        if (c + 1 < NC)
            load_stage(smem + SMEM_STAGE0 + ((c + 1) & 1) * STAGE_BYTES,
                       Ah, Al, Bh, Bl, arow0, brow0, K, (size_t)(c + 1) * KC, tid);

        uint32_t stg_u = sb + SMEM_STAGE0 + (c & 1) * STAGE_BYTES;
#pragma unroll
        for (int ks = 0; ks < KC / 16; ++ks) {
            uint32_t ah[4][4], al[4][4], bh[4][2], bl[4][2];
#pragma unroll
            for (int mt = 0; mt < 4; ++mt) {
                uint32_t r = m_off + mt * 16 + a_row;
                uint32_t addr = stg_u + (r << 7) + ((ks * 32 + a_kx) ^ xorv);
                LDSM_X4(ah[mt], addr + OFF_AH);
                LDSM_X4(al[mt], addr + OFF_AL);
            }
#pragma unroll
            for (int np = 0; np < 2; ++np) {
                uint32_t r = n_off + np * 16 + b_row;
                uint32_t addr = stg_u + (r << 7) + ((ks * 32 + b_kx) ^ xorv);
                uint32_t t0[4], t1[4];
                LDSM_X4(t0, addr + OFF_BH);
                LDSM_X4(t1, addr + OFF_BL);
                bh[np * 2][0] = t0[0]; bh[np * 2][1] = t0[1];
                bh[np * 2 + 1][0] = t0[2]; bh[np * 2 + 1][1] = t0[3];
                bl[np * 2][0] = t1[0]; bl[np * 2][1] = t1[1];
                bl[np * 2 + 1][0] = t1[2]; bl[np * 2 + 1][1] = t1[3];
            }
#pragma unroll
            for (int mt = 0; mt < 4; ++mt)
#pragma unroll
                for (int nt = 0; nt < 4; ++nt) {
                    mma16816(acc[mt][nt], ah[mt], bh[nt]);   // hi*hi
                    mma16816(acc[mt][nt], ah[mt], bl[nt]);   // hi*lo
                    mma16816(acc[mt][nt], al[mt], bh[nt]);   // lo*hi
                }
        }
    }

    // epilogue: thread holds D[g][2t],D[g][2t+1] (c0,c1) and D[g+8][...] (c2,c3)
    int g = lid >> 2, t2 = (lid & 3) * 2;
#pragma unroll
    for (int mt = 0; mt < 4; ++mt) {
#pragma unroll
        for (int nt = 0; nt < 4; ++nt) {
            size_t col = ncol0 + n_off + nt * 8 + t2;
            size_t row0 = arow0 + m_off + mt * 16 + g;
            size_t row1 = row0 + 8;
            float c0 = acc[mt][nt][0], c1 = acc[mt][nt][1];
            float c2 = acc[mt][nt][2], c3 = acc[mt][nt][3];
            if (GELU_SPLIT) {
                float g0 = gelu_tanh(c0), g1 = gelu_tanh(c1);
                float g2 = gelu_tanh(c2), g3 = gelu_tanh(c3);
                bf16 h0 = __float2bfloat16(g0), h1 = __float2bfloat16(g1);
                bf16 h2 = __float2bfloat16(g2), h3 = __float2bfloat16(g3);
                __nv_bfloat162 hp0, lp0, hp1, lp1;
                hp0.x = h0; hp0.y = h1;
                lp0.x = __float2bfloat16(g0 - __bfloat162float(h0));
                lp0.y = __float2bfloat16(g1 - __bfloat162float(h1));
                hp1.x = h2; hp1.y = h3;
                lp1.x = __float2bfloat16(g2 - __bfloat162float(h2));
                lp1.y = __float2bfloat16(g3 - __bfloat162float(h3));
                *(__nv_bfloat162*)(Oh + row0 * (size_t)ldo + col) = hp0;
                *(__nv_bfloat162*)(Ol + row0 * (size_t)ldo + col) = lp0;
                *(__nv_bfloat162*)(Oh + row1 * (size_t)ldo + col) = hp1;
                *(__nv_bfloat162*)(Ol + row1 * (size_t)ldo + col) = lp1;
            } else {
                float2 v0 = make_float2(c0, c1), v1 = make_float2(c2, c3);
                *(float2*)(Of + row0 * (size_t)ldo + col) = v0;
                *(float2*)(Of + row1 * (size_t)ldo + col) = v1;
            }
        }
    }
#endif
}

// ---------------- launch ----------------
extern "C" void kernel_launch(void* const* d_in, const int* in_sizes, int n_in,
                              void* d_out, int out_size) {
    (void)in_sizes; (void)n_in; (void)out_size;
    const float* x  = (const float*)d_in[0];
    const float* w1 = (const float*)d_in[1];   // [E, H, F]
    const float* w2 = (const float*)d_in[2];   // [E, F, H]
    float* out = (float*)d_out;                // [T, H]

    bf16 *xh, *xl, *w1h, *w1l, *w2h, *w2l, *ih, *il;
    cudaGetSymbolAddress((void**)&xh,  g_xh);
    cudaGetSymbolAddress((void**)&xl,  g_xl);
    cudaGetSymbolAddress((void**)&w1h, g_w1h);
    cudaGetSymbolAddress((void**)&w1l, g_w1l);
    cudaGetSymbolAddress((void**)&w2h, g_w2h);
    cudaGetSymbolAddress((void**)&w2l, g_w2l);
    cudaGetSymbolAddress((void**)&ih,  g_ih);
    cudaGetSymbolAddress((void**)&il,  g_il);

    int n4 = T_ * H_ / 4;
    k_split<<<(n4 + 255) / 256, 256>>>((const float4*)x,
                                       (__nv_bfloat162*)xh, (__nv_bfloat162*)xl, n4);
    dim3 tb(32, 8);
    k_transpose_split<<<dim3(F_ / 32, H_ / 32, E_), tb>>>(w1, w1h, w1l, H_, F_); // -> [E,F,H]
    k_transpose_split<<<dim3(H_ / 32, F_ / 32, E_), tb>>>(w2, w2h, w2l, F_, H_); // -> [E,H,F]

    cudaFuncSetAttribute(k_gemm<true>,  cudaFuncAttributeMaxDynamicSharedMemorySize, SMEM_TOTAL);
    cudaFuncSetAttribute(k_gemm<false>, cudaFuncAttributeMaxDynamicSharedMemorySize, SMEM_TOTAL);

    // GEMM1: I = gelu(X @ W1) -> bf16 hi/lo, [T, F]
    k_gemm<true><<<dim3(F_ / NT, TPE_ / MT, E_), 256, SMEM_TOTAL>>>(
        xh, xl, w1h, w1l, H_, TPE_, F_, ih, il, nullptr, F_);
    // GEMM2: out = I @ W2 -> fp32, [T, H]
    k_gemm<false><<<dim3(H_ / NT, TPE_ / MT, E_), 256, SMEM_TOTAL>>>(
        ih, il, w2h, w2l, F_, TPE_, H_, nullptr, nullptr, out, H_);
}